// round 14
// baseline (speedup 1.0000x reference)
#include <cuda_runtime.h>
#include <cuda_bf16.h>
#include <math.h>

#define TPB   256
#define NBLK  592                     // K1: 4 blocks/SM * 148 SMs -> all resident
#define GT    (NBLK * TPB)

// ---------------- scratch (static device globals; no allocation) ----------------
__device__ float g_t0B[2][196608];   // stage0 WH-resized [tensor][(b,c,d)][16*16]
__device__ float g_t1B[2][49152];    // stage1 WH-resized [tensor][(b,c,d)][8*8]
__device__ float g_r0[2][49152];     // stage0 resized [tensor][B=4][3][4096]
__device__ float g_r1[2][6144];      // stage1 resized [tensor][B=4][3][512]
__device__ unsigned long long g_k0[16384];  // stage0 argmin keys [B][4096]
__device__ unsigned long long g_k1[2048];   // stage1 argmin keys [B][512]
__device__ double g_acc[2];          // per-stage cos sums
__device__ unsigned g_bar;           // K1 barrier arrival counter (self-resets)
__device__ unsigned g_gen;           // K1 barrier generation (monotone across replays)
__device__ unsigned g_done;          // cos completion counter (reset each run)

// ---------------- grid-wide barrier for K1 (all NBLK blocks resident) -----------
__device__ __forceinline__ void grid_sync() {
    __syncthreads();
    if (threadIdx.x == 0) {
        __threadfence();
        unsigned gen = *(volatile unsigned*)&g_gen;
        if (atomicAdd(&g_bar, 1u) == NBLK - 1u) {
            atomicExch(&g_bar, 0u);
            __threadfence();
            atomicAdd(&g_gen, 1u);                // release
        } else {
            while (*(volatile unsigned*)&g_gen == gen) __nanosleep(64);
        }
        __threadfence();
    }
    __syncthreads();
}

// ================= K1: persistent resize (fused W+H per plane, then D) ==========
// jax triangle antialias: kernel_scale R = 64/Lout, half-pixel centers,
// pre-normalized weights over in-range taps (== compute_weight_mat).
__global__ void __launch_bounds__(TPB, 4)
resize_kernel(const float* __restrict__ cs, const float* __restrict__ ct)
{
    __shared__ float4 s_plane4[1024];            // one 64x64 input plane (16KB)
    __shared__ float  s_o0[64 * 16];             // stage0 W-resized [h][i] (4KB)
    __shared__ float  s_o1[64 * 8];              // stage1 W-resized [h][i] (2KB)
    __shared__ float  s_w0[16 * 8];              // stage0 weights [i][k]
    __shared__ float  s_w1[8 * 16];              // stage1 weights [i][k]
    __shared__ int    s_j0[16], s_j1[8];
    float* s_plane = (float*)s_plane4;
    const int gid = blockIdx.x * TPB + threadIdx.x;

    // ---- weight tables (once per block) ----
    if (threadIdx.x < 24) {
        int stage = threadIdx.x >= 16;
        int i = stage ? threadIdx.x - 16 : threadIdx.x;
        float R    = stage ? 8.0f : 4.0f;
        float invR = stage ? 0.125f : 0.25f;
        int NT     = stage ? 16 : 8;
        float sf = (i + 0.5f) * R - 0.5f;
        int jlo = (int)floorf(sf - R) + 1;
        if (jlo < 0) jlo = 0;
        if (jlo > 64 - NT) jlo = 64 - NT;
        float wv[16]; float ws = 0.0f;
        for (int k = 0; k < NT; ++k) {
            float w = 1.0f - fabsf((float)(jlo + k) - sf) * invR;
            w = fmaxf(w, 0.0f);
            ws += w; wv[k] = w;
        }
        for (int k = 0; k < NT; ++k) {
            float wn = wv[k] / ws;
            if (stage) s_w1[i * 16 + k] = wn; else s_w0[i * 8 + k] = wn;
        }
        if (stage) s_j1[i] = jlo; else s_j0[i] = jlo;
    }

    // ---- init keys/accumulators (no dependency on resize; overlaps) ----
    for (int i = gid; i < 16384; i += GT) g_k0[i] = ~0ULL;
    for (int i = gid; i < 2048;  i += GT) g_k1[i] = ~0ULL;
    if (gid < 2) g_acc[gid] = 0.0;
    if (gid == 0) g_done = 0u;
    __syncthreads();                              // weight tables ready

    // ---- phase 1: fused W+H resize, both stages, one plane load ----
    // unit = (tensor, plane pc=(b,c,d)); 2*768 = 1536 units
    for (int u = blockIdx.x; u < 1536; u += NBLK) {
        int tensor = u / 768;
        int pc     = u - tensor * 768;
        const float* pb = (tensor ? ct : cs) + (size_t)pc * 4096;

        __syncthreads();                          // previous unit's readers done
        for (int t = threadIdx.x; t < 1024; t += TPB)
            s_plane4[t] = ((const float4*)pb)[t];
        __syncthreads();

        // W-resize stage0: [64][16]
        for (int t = threadIdx.x; t < 1024; t += TPB) {
            int h = t >> 4, i = t & 15;
            const float* row = s_plane + h * 64 + s_j0[i];
            const float* w = s_w0 + i * 8;
            float a = 0.0f;
#pragma unroll
            for (int k = 0; k < 8; ++k) a = fmaf(w[k], row[k], a);
            s_o0[t] = a;
        }
        // W-resize stage1: [64][8]
        for (int t = threadIdx.x; t < 512; t += TPB) {
            int h = t >> 3, i = t & 7;
            const float* row = s_plane + h * 64 + s_j1[i];
            const float* w = s_w1 + i * 16;
            float a = 0.0f;
#pragma unroll
            for (int k = 0; k < 16; ++k) a = fmaf(w[k], row[k], a);
            s_o1[t] = a;
        }
        __syncthreads();

        // H-resize stage0 -> g_t0B [pc][j*16+i]
        {
            int j = threadIdx.x >> 4, i = threadIdx.x & 15;
            const float* w = s_w0 + j * 8;
            int jl = s_j0[j];
            float a = 0.0f;
#pragma unroll
            for (int k = 0; k < 8; ++k) a = fmaf(w[k], s_o0[(jl + k) * 16 + i], a);
            g_t0B[tensor][pc * 256 + threadIdx.x] = a;
        }
        // H-resize stage1 -> g_t1B [pc][j*8+i]
        if (threadIdx.x < 64) {
            int j = threadIdx.x >> 3, i = threadIdx.x & 7;
            const float* w = s_w1 + j * 16;
            int jl = s_j1[j];
            float a = 0.0f;
#pragma unroll
            for (int k = 0; k < 16; ++k) a = fmaf(w[k], s_o1[(jl + k) * 8 + i], a);
            g_t1B[tensor][pc * 64 + threadIdx.x] = a;
        }
    }
    grid_sync();

    // ---- phase 2: D-resize (reads L2-resident g_t0B/g_t1B) ----
    {
        const int T0 = 98304;                     // 2 * 12 * 16 * 256
        const int TOT = T0 + 12288;               // + 2 * 12 * 8 * 64
        for (int idx = gid; idx < TOT; idx += GT) {
            if (idx < T0) {
                int tensor = idx / 49152, l = idx % 49152;
                int bc = l >> 12, rest = l & 4095, dp = rest >> 8, hw = rest & 255;
                const float* src = g_t0B[tensor] + (bc * 64 + s_j0[dp]) * 256 + hw;
                const float* w = s_w0 + dp * 8;
                float a = 0.0f;
#pragma unroll
                for (int k = 0; k < 8; ++k) a = fmaf(w[k], src[k * 256], a);
                g_r0[tensor][bc * 4096 + dp * 256 + hw] = a;
            } else {
                int r = idx - T0;
                int tensor = r / 6144, l = r % 6144;
                int bc = l >> 9, rest = l & 511, dp = rest >> 6, hw = rest & 63;
                const float* src = g_t1B[tensor] + (bc * 64 + s_j1[dp]) * 64 + hw;
                const float* w = s_w1 + dp * 16;
                float a = 0.0f;
#pragma unroll
                for (int k = 0; k < 16; ++k) a = fmaf(w[k], src[k * 64], a);
                g_r1[tensor][bc * 512 + dp * 64 + hw] = a;
            }
        }
    }
}

// ================= K2: standalone nearest neighbor (packed fminf argmin) ========
// score = 0.5*|b|^2 - a.b (argmin-equivalent to |a-b|^2). Within a tile, 7 low
// mantissa bits carry the tile-local index and fminf tracks the min (5 instr/
// pair, no select chain). Cross-tile merge via atomicMin on
// (sortable float bits << 32) | m; lower m wins ties (jnp.argmin semantics).
template<int N, int NPT, int NM>
__device__ __forceinline__ void nn_unit(const float* __restrict__ A,
                                        const float* __restrict__ Bp,
                                        unsigned long long* __restrict__ keys,
                                        int b, int ytile, int mtile, float4* sB)
{
    int m0 = mtile * NM;
    const float* bx = Bp + (size_t)b * 3 * N;
    for (int i = threadIdx.x; i < NM; i += TPB) {
        int m = m0 + i;
        float x = bx[m], y = bx[N + m], z = bx[2 * N + m];
        sB[i] = make_float4(x, y, z, 0.5f * (x * x + y * y + z * z));
    }
    __syncthreads();

    const float* ax = A + (size_t)b * 3 * N;
    int nb = ytile * (TPB * NPT) + threadIdx.x;

    float px[NPT], py[NPT], pz[NPT], best[NPT];
#pragma unroll
    for (int k = 0; k < NPT; ++k) {
        int n = nb + k * TPB;
        px[k] = ax[n]; py[k] = ax[N + n]; pz[k] = ax[2 * N + n];
        best[k] = 3.402823466e38f;
    }

#pragma unroll 4
    for (int i = 0; i < NM; ++i) {
        float4 q = sB[i];
#pragma unroll
        for (int k = 0; k < NPT; ++k) {
            float s = fmaf(-px[k], q.x, q.w);
            s = fmaf(-py[k], q.y, s);
            s = fmaf(-pz[k], q.z, s);
            unsigned us = (__float_as_uint(s) & 0xFFFFFF80u) | (unsigned)i;  // LOP3
            best[k] = fminf(best[k], __uint_as_float(us));                    // FMNMX
        }
    }

#pragma unroll
    for (int k = 0; k < NPT; ++k) {
        int n = nb + k * TPB;
        unsigned u = __float_as_uint(best[k]);
        int i = (int)(u & 0x7Fu);
        unsigned su = (u & 0x80000000u) ? ~u : (u | 0x80000000u);  // order-preserving
        unsigned long long key = ((unsigned long long)su << 32) | (unsigned)(m0 + i);
        atomicMin(&keys[(size_t)b * N + n], key);
    }
}

// grid 544: u<512 -> stage0 (b(4) x ytile(4) x mtile(32), NM=128, NPT=4);
//           else  -> stage1 (b(4) x mtile(8), NM=64, NPT=2)
__global__ void nn_kernel()
{
    __shared__ float4 sB[128];
    int u = blockIdx.x;
    if (u < 512) {
        nn_unit<4096, 4, 128>(g_r0[0], g_r0[1], g_k0,
                              u & 3, (u >> 2) & 3, u >> 4, sB);
    } else {
        int v = u - 512;
        nn_unit<512, 2, 64>(g_r1[0], g_r1[1], g_k1,
                            v & 3, 0, v >> 2, sB);
    }
}

// ================= K3: cosine + reduction + in-kernel finalize ==================
// desc layout [B][32][N]; flattened-spatial element (b,n,c) = desc[b,c,n].
template<int N>
__device__ __forceinline__ float cos_body(const float* __restrict__ sd,
                                          const float* __restrict__ td,
                                          const unsigned long long* __restrict__ keys,
                                          int b, int xb)
{
    int n = xb * TPB + threadIdx.x;
    int m = (int)(unsigned)(keys[(size_t)b * N + n] & 0xFFFFFFFFull);

    const float* s = sd + (size_t)b * 32 * N;
    const float* t = td + (size_t)b * 32 * N;
    float dot = 0.f, ns = 0.f, ng = 0.f;
#pragma unroll
    for (int c = 0; c < 32; ++c) {
        float x = s[(size_t)c * N + n];
        float y = t[(size_t)c * N + m];
        dot = fmaf(x, y, dot);
        ns  = fmaf(x, x, ns);
        ng  = fmaf(y, y, ng);
    }
    return dot / (fmaxf(sqrtf(ns), 1e-8f) * fmaxf(sqrtf(ng), 1e-8f));
}

// grid 72: u<64 -> stage0 (b(4) x xb(16)); else stage1 (b(4) x xb(2))
__global__ void cos_kernel(const float* __restrict__ sd0, const float* __restrict__ td0,
                           const float* __restrict__ sd1, const float* __restrict__ td1,
                           float* __restrict__ out)
{
    __shared__ float wsum[TPB / 32];
    int u = blockIdx.x;
    int stage = (u < 64) ? 0 : 1;
    float cv;
    if (stage == 0) cv = cos_body<4096>(sd0, td0, g_k0, u & 3, u >> 2);
    else            cv = cos_body<512> (sd1, td1, g_k1, (u - 64) & 3, (u - 64) >> 2);

    for (int o = 16; o > 0; o >>= 1) cv += __shfl_down_sync(0xffffffffu, cv, o);
    if ((threadIdx.x & 31) == 0) wsum[threadIdx.x >> 5] = cv;
    __syncthreads();
    if (threadIdx.x < TPB / 32) {
        float v = wsum[threadIdx.x];
        for (int o = (TPB / 64); o > 0; o >>= 1) v += __shfl_down_sync(0xffu, v, o);
        if (threadIdx.x == 0) {
            atomicAdd(&g_acc[stage], (double)v);
            __threadfence();
            if (atomicAdd(&g_done, 1u) == 71u) {          // last cos block
                double a0 = atomicAdd(&g_acc[0], 0.0);
                double a1 = atomicAdd(&g_acc[1], 0.0);
                double l0 = 1.0 - a0 / (4.0 * 4096.0);
                double l1 = 1.0 - a1 / (4.0 * 512.0);
                out[0] = (float)(0.5 * (l0 + l1));
            }
        }
    }
}

// ---------------- launch (3 kernel launches) -------------------------------------
extern "C" void kernel_launch(void* const* d_in, const int* in_sizes, int n_in,
                              void* d_out, int out_size)
{
    const float* cs  = (const float*)d_in[0];  // canonical_source [4,3,64,64,64]
    const float* ct  = (const float*)d_in[1];  // canonical_target
    const float* sd0 = (const float*)d_in[2];  // src_desc0 [4,32,16,16,16]
    const float* td0 = (const float*)d_in[3];
    const float* sd1 = (const float*)d_in[4];  // src_desc1 [4,32,8,8,8]
    const float* td1 = (const float*)d_in[5];
    float* out = (float*)d_out;

    resize_kernel<<<NBLK, TPB>>>(cs, ct);
    nn_kernel<<<544, TPB>>>();
    cos_kernel<<<72, TPB>>>(sd0, td0, sd1, td1, out);
}